// round 14
// baseline (speedup 1.0000x reference)
#include <cuda_runtime.h>
#include <cstdint>

// Output: (BATCH=256, SEQ=512, DIM=64) fp32.
// inputs: (256,512) fp32; tables: (3,100000,64) fp32; table_ids: (512) int32.
//
// Theory: the ~21MB unique gather set is evicted from L2 every replay by the
// 33.5MB output-store sweep -> all gathers go to DRAM. Fix with residency:
//   gather loads : ld.global.nc.L2::evict_last.v8.b32 (256-bit, pin in L2)
//   output stores: st.global.cs (evict-first stream)
// ptxas requires v8.b32/v4.b64 for evict_last -> 8 threads per 64-float row,
// 32B per thread per slot.

#define BATCH 256
#define SEQ   512
#define DIM   64
#define VOCAB 100000
#define ROWS_PER_BLK 64
#define THREADS 128
#define U 4                       // 64 rows * 8 slots / 128 threads

__global__ void __launch_bounds__(THREADS)
emb_gather_kernel(const float* __restrict__ inputs,
                  const float* __restrict__ tables,
                  const int*   __restrict__ table_ids,
                  float4*      __restrict__ out)
{
    __shared__ int   s_off[ROWS_PER_BLK];  // float-index into tables, or -1
    __shared__ float s_val[ROWS_PER_BLK];

    const int tid  = threadIdx.x;
    const int row0 = blockIdx.x * ROWS_PER_BLK;

    // ---- Phase 1: per-row descriptors ----
    if (tid < ROWS_PER_BLK) {
        int row = row0 + tid;
        int s   = row & (SEQ - 1);
        float v = __ldg(&inputs[row]);
        int  tb = __ldg(&table_ids[s]);
        s_val[tid] = v;
        s_off[tid] = (tb >= 0) ? (tb * VOCAB + (int)v) * DIM : -1;
    }
    __syncthreads();

    int   off[U];
    float val[U];
    unsigned long long addr[U];
    #pragma unroll
    for (int k = 0; k < U; k++) {
        int j     = k * THREADS + tid;   // 32B slot: [0, 512)
        int rl    = j >> 3;              // local row
        int lane8 = j & 7;               // which 32B chunk of the 256B row
        off[k] = s_off[rl];
        val[k] = s_val[rl];
        int safe = off[k] >= 0 ? off[k] : 0;   // numeric rows -> table row 0
        addr[k] = (unsigned long long)tables
                + ((unsigned long long)(unsigned)(safe + lane8 * 8) << 2);
    }

    // ---- 4 x 256-bit LDG back-to-back, L2::evict_last ----
    unsigned x[32];
    asm volatile(
        "ld.global.nc.L2::evict_last.v8.b32 {%0,%1,%2,%3,%4,%5,%6,%7},         [%32];\n\t"
        "ld.global.nc.L2::evict_last.v8.b32 {%8,%9,%10,%11,%12,%13,%14,%15},   [%33];\n\t"
        "ld.global.nc.L2::evict_last.v8.b32 {%16,%17,%18,%19,%20,%21,%22,%23}, [%34];\n\t"
        "ld.global.nc.L2::evict_last.v8.b32 {%24,%25,%26,%27,%28,%29,%30,%31}, [%35];\n\t"
        : "=r"(x[0]),  "=r"(x[1]),  "=r"(x[2]),  "=r"(x[3]),
          "=r"(x[4]),  "=r"(x[5]),  "=r"(x[6]),  "=r"(x[7]),
          "=r"(x[8]),  "=r"(x[9]),  "=r"(x[10]), "=r"(x[11]),
          "=r"(x[12]), "=r"(x[13]), "=r"(x[14]), "=r"(x[15]),
          "=r"(x[16]), "=r"(x[17]), "=r"(x[18]), "=r"(x[19]),
          "=r"(x[20]), "=r"(x[21]), "=r"(x[22]), "=r"(x[23]),
          "=r"(x[24]), "=r"(x[25]), "=r"(x[26]), "=r"(x[27]),
          "=r"(x[28]), "=r"(x[29]), "=r"(x[30]), "=r"(x[31])
        : "l"(addr[0]), "l"(addr[1]), "l"(addr[2]), "l"(addr[3]));

    float4* oblk = out + (size_t)row0 * (DIM / 4);
    #pragma unroll
    for (int k = 0; k < U; k++) {
        int j = k * THREADS + tid;      // 32B slot -> two float4 slots
        float4 r0, r1;
        if (off[k] >= 0) {
            r0 = make_float4(__uint_as_float(x[8*k+0]), __uint_as_float(x[8*k+1]),
                             __uint_as_float(x[8*k+2]), __uint_as_float(x[8*k+3]));
            r1 = make_float4(__uint_as_float(x[8*k+4]), __uint_as_float(x[8*k+5]),
                             __uint_as_float(x[8*k+6]), __uint_as_float(x[8*k+7]));
        } else {
            r0 = make_float4(val[k], val[k], val[k], val[k]);
            r1 = r0;
        }
        __stcs(oblk + j * 2 + 0, r0);
        __stcs(oblk + j * 2 + 1, r1);
    }
}

extern "C" void kernel_launch(void* const* d_in, const int* in_sizes, int n_in,
                              void* d_out, int out_size)
{
    const float* inputs    = (const float*)d_in[0];
    const float* tables    = (const float*)d_in[1];
    const int*   table_ids = (const int*)d_in[2];
    float4*      out       = (float4*)d_out;

    int blocks = (BATCH * SEQ) / ROWS_PER_BLK;   // 2048
    emb_gather_kernel<<<blocks, THREADS>>>(inputs, tables, table_ids, out);
}

// round 15
// speedup vs baseline: 1.3819x; 1.3819x over previous
#include <cuda_runtime.h>
#include <cstdint>

// Output: (BATCH=256, SEQ=512, DIM=64) fp32.
// inputs: (256,512) fp32; tables: (3,100000,64) fp32; table_ids: (512) int32.
//
// R8 structure (best: 10.7us) + L2 residency control:
//  - gather loads: ld.global.nc.L2::cache_hint.v4.f32 with a
//    createpolicy.fractional.L2::evict_last policy (works with .v4, unlike
//    the static .L2::evict_last modifier which requires .v8).
//  - output stores: PLAIN st.global (not .cs) -> output lines stay
//    L2-resident and are re-dirtied each graph replay instead of being
//    evicted + written back to DRAM every time.
// Hot set (21MB gathers + 33.5MB output) fits in 126MB L2.

#define BATCH 256
#define SEQ   512
#define DIM   64
#define VOCAB 100000
#define ROWS_PER_BLK 64
#define THREADS 128
#define U 8

__global__ void __launch_bounds__(THREADS)
emb_gather_kernel(const float* __restrict__ inputs,
                  const float* __restrict__ tables,
                  const int*   __restrict__ table_ids,
                  float4*      __restrict__ out)
{
    __shared__ int   s_off[ROWS_PER_BLK];  // float4-index into tables, or -1
    __shared__ float s_val[ROWS_PER_BLK];

    const int tid  = threadIdx.x;
    const int row0 = blockIdx.x * ROWS_PER_BLK;

    // ---- Phase 1: per-row descriptors ----
    if (tid < ROWS_PER_BLK) {
        int row = row0 + tid;
        int s   = row & (SEQ - 1);
        float v = __ldg(&inputs[row]);
        int  tb = __ldg(&table_ids[s]);
        s_val[tid] = v;
        s_off[tid] = (tb >= 0) ? (tb * VOCAB + (int)v) * (DIM / 4) : -1;
    }
    __syncthreads();

    int   off[U];
    float val[U];
    unsigned long long addr[U];
    #pragma unroll
    for (int k = 0; k < U; k++) {
        int j    = k * THREADS + tid;
        int rl   = j >> 4;
        int lane = j & 15;
        off[k] = s_off[rl];
        val[k] = s_val[rl];
        int safe = off[k] >= 0 ? off[k] : 0;     // numeric rows -> table row 0
        addr[k] = (unsigned long long)tables + ((unsigned long long)(unsigned)(safe + lane) << 4);
    }

    // L2 evict_last policy for the gather stream
    unsigned long long pol;
    asm("createpolicy.fractional.L2::evict_last.b64 %0, 1.0;" : "=l"(pol));

    // ---- 8 LDG.128 back-to-back with evict_last cache hint (MLP=8) ----
    float x[32];
    asm volatile(
        "ld.global.nc.L2::cache_hint.v4.f32 {%0,%1,%2,%3},     [%32], %40;\n\t"
        "ld.global.nc.L2::cache_hint.v4.f32 {%4,%5,%6,%7},     [%33], %40;\n\t"
        "ld.global.nc.L2::cache_hint.v4.f32 {%8,%9,%10,%11},   [%34], %40;\n\t"
        "ld.global.nc.L2::cache_hint.v4.f32 {%12,%13,%14,%15}, [%35], %40;\n\t"
        "ld.global.nc.L2::cache_hint.v4.f32 {%16,%17,%18,%19}, [%36], %40;\n\t"
        "ld.global.nc.L2::cache_hint.v4.f32 {%20,%21,%22,%23}, [%37], %40;\n\t"
        "ld.global.nc.L2::cache_hint.v4.f32 {%24,%25,%26,%27}, [%38], %40;\n\t"
        "ld.global.nc.L2::cache_hint.v4.f32 {%28,%29,%30,%31}, [%39], %40;\n\t"
        : "=f"(x[0]),  "=f"(x[1]),  "=f"(x[2]),  "=f"(x[3]),
          "=f"(x[4]),  "=f"(x[5]),  "=f"(x[6]),  "=f"(x[7]),
          "=f"(x[8]),  "=f"(x[9]),  "=f"(x[10]), "=f"(x[11]),
          "=f"(x[12]), "=f"(x[13]), "=f"(x[14]), "=f"(x[15]),
          "=f"(x[16]), "=f"(x[17]), "=f"(x[18]), "=f"(x[19]),
          "=f"(x[20]), "=f"(x[21]), "=f"(x[22]), "=f"(x[23]),
          "=f"(x[24]), "=f"(x[25]), "=f"(x[26]), "=f"(x[27]),
          "=f"(x[28]), "=f"(x[29]), "=f"(x[30]), "=f"(x[31])
        : "l"(addr[0]), "l"(addr[1]), "l"(addr[2]), "l"(addr[3]),
          "l"(addr[4]), "l"(addr[5]), "l"(addr[6]), "l"(addr[7]),
          "l"(pol));

    float4* oblk = out + (size_t)row0 * (DIM / 4);
    #pragma unroll
    for (int k = 0; k < U; k++) {
        float4 r;
        if (off[k] >= 0) {
            r = make_float4(x[4*k], x[4*k+1], x[4*k+2], x[4*k+3]);
        } else {
            r = make_float4(val[k], val[k], val[k], val[k]);
        }
        oblk[k * THREADS + tid] = r;    // default policy: keep output in L2
    }
}

extern "C" void kernel_launch(void* const* d_in, const int* in_sizes, int n_in,
                              void* d_out, int out_size)
{
    const float* inputs    = (const float*)d_in[0];
    const float* tables    = (const float*)d_in[1];
    const int*   table_ids = (const int*)d_in[2];
    float4*      out       = (float4*)d_out;

    int blocks = (BATCH * SEQ) / ROWS_PER_BLK;   // 2048
    emb_gather_kernel<<<blocks, THREADS>>>(inputs, tables, table_ids, out);
}

// round 16
// speedup vs baseline: 1.4149x; 1.0239x over previous
#include <cuda_runtime.h>
#include <cstdint>

// Output: (BATCH=256, SEQ=512, DIM=64) fp32.
// inputs: (256,512) fp32; tables: (3,100000,64) fp32; table_ids: (512) int32.
//
// Consolidated best design: smem row descriptors, asm-batched 8x LDG.128
// gathers (forced MLP=8), plain coalesced float4 stores. This round: 128
// rows / 256 threads per block (halves block count -> halves per-block
// descriptor-chain + sync overhead chip-wide).

#define BATCH 256
#define SEQ   512
#define DIM   64
#define VOCAB 100000
#define ROWS_PER_BLK 128
#define THREADS 256
#define U 8

__global__ void __launch_bounds__(THREADS)
emb_gather_kernel(const float* __restrict__ inputs,
                  const float* __restrict__ tables,
                  const int*   __restrict__ table_ids,
                  float4*      __restrict__ out)
{
    __shared__ int   s_off[ROWS_PER_BLK];  // float4-index into tables, or -1
    __shared__ float s_val[ROWS_PER_BLK];

    const int tid  = threadIdx.x;
    const int row0 = blockIdx.x * ROWS_PER_BLK;

    // ---- Phase 1: per-row descriptors ----
    if (tid < ROWS_PER_BLK) {
        int row = row0 + tid;
        int s   = row & (SEQ - 1);
        float v = __ldg(&inputs[row]);
        int  tb = __ldg(&table_ids[s]);
        s_val[tid] = v;
        s_off[tid] = (tb >= 0) ? (tb * VOCAB + (int)v) * (DIM / 4) : -1;
    }
    __syncthreads();

    int   off[U];
    float val[U];
    unsigned long long addr[U];
    #pragma unroll
    for (int k = 0; k < U; k++) {
        int j    = k * THREADS + tid;
        int rl   = j >> 4;
        int lane = j & 15;
        off[k] = s_off[rl];
        val[k] = s_val[rl];
        int safe = off[k] >= 0 ? off[k] : 0;     // numeric rows -> table row 0
        addr[k] = (unsigned long long)tables + ((unsigned long long)(unsigned)(safe + lane) << 4);
    }

    // ---- 8 LDG.128 back-to-back (forced MLP=8) ----
    float x[32];
    asm volatile(
        "ld.global.nc.v4.f32 {%0,%1,%2,%3},     [%32];\n\t"
        "ld.global.nc.v4.f32 {%4,%5,%6,%7},     [%33];\n\t"
        "ld.global.nc.v4.f32 {%8,%9,%10,%11},   [%34];\n\t"
        "ld.global.nc.v4.f32 {%12,%13,%14,%15}, [%35];\n\t"
        "ld.global.nc.v4.f32 {%16,%17,%18,%19}, [%36];\n\t"
        "ld.global.nc.v4.f32 {%20,%21,%22,%23}, [%37];\n\t"
        "ld.global.nc.v4.f32 {%24,%25,%26,%27}, [%38];\n\t"
        "ld.global.nc.v4.f32 {%28,%29,%30,%31}, [%39];\n\t"
        : "=f"(x[0]),  "=f"(x[1]),  "=f"(x[2]),  "=f"(x[3]),
          "=f"(x[4]),  "=f"(x[5]),  "=f"(x[6]),  "=f"(x[7]),
          "=f"(x[8]),  "=f"(x[9]),  "=f"(x[10]), "=f"(x[11]),
          "=f"(x[12]), "=f"(x[13]), "=f"(x[14]), "=f"(x[15]),
          "=f"(x[16]), "=f"(x[17]), "=f"(x[18]), "=f"(x[19]),
          "=f"(x[20]), "=f"(x[21]), "=f"(x[22]), "=f"(x[23]),
          "=f"(x[24]), "=f"(x[25]), "=f"(x[26]), "=f"(x[27]),
          "=f"(x[28]), "=f"(x[29]), "=f"(x[30]), "=f"(x[31])
        : "l"(addr[0]), "l"(addr[1]), "l"(addr[2]), "l"(addr[3]),
          "l"(addr[4]), "l"(addr[5]), "l"(addr[6]), "l"(addr[7]));

    float4* oblk = out + (size_t)row0 * (DIM / 4);
    #pragma unroll
    for (int k = 0; k < U; k++) {
        float4 r;
        if (off[k] >= 0) {
            r = make_float4(x[4*k], x[4*k+1], x[4*k+2], x[4*k+3]);
        } else {
            r = make_float4(val[k], val[k], val[k], val[k]);
        }
        oblk[k * THREADS + tid] = r;
    }
}

extern "C" void kernel_launch(void* const* d_in, const int* in_sizes, int n_in,
                              void* d_out, int out_size)
{
    const float* inputs    = (const float*)d_in[0];
    const float* tables    = (const float*)d_in[1];
    const int*   table_ids = (const int*)d_in[2];
    float4*      out       = (float4*)d_out;

    int blocks = (BATCH * SEQ) / ROWS_PER_BLK;   // 1024
    emb_gather_kernel<<<blocks, THREADS>>>(inputs, tables, table_ids, out);
}